// round 9
// baseline (speedup 1.0000x reference)
#include <cuda_runtime.h>
#include <cstdint>

// Problem constants
constexpr int B  = 2;
constexpr int CI = 4;      // instance channels: 1,3,5,7
constexpr int DD = 128, HH = 128, WW = 128;
constexpr int ROWS = B * CI * DD * HH;   // 131072 bit-rows of 128 bits
constexpr int WPR  = WW / 32;            // 4 uint32 words per row

// Device scratch (static; no allocation)
__device__ unsigned int g_tbits[ROWS * WPR];  // packed targets (2 MB)
__device__ unsigned int g_e2[ROWS * WPR];     // double-eroded targets (2 MB)
__device__ double g_num, g_den;
__device__ float g_instMask[B * CI];
__device__ float g_nActive[B];
__device__ unsigned int g_done;               // zero-init; reset by last block

// ---------------------------------------------------------------------------
// Mask decode (dtype-robust: bool bytes / int32 / f32) — runs on one thread
// ---------------------------------------------------------------------------
__device__ void decode_mask_and_zero(const void* maskp) {
    g_num = 0.0; g_den = 0.0;

    const unsigned char* b8 = (const unsigned char*)maskp;
    bool vb = true, bool_definitely = false;
    unsigned char bb[16];
    for (int i = 0; i < 16; i++) {
        bb[i] = b8[i];
        if (bb[i] > 1) vb = false;     // f32 1.0f bytes {0,0,128,63} trip this
    }
    if (vb) {
        for (int i = 0; i < 16; i++)
            if (bb[i] == 1 && (i & 3) != 0) bool_definitely = true;
    }

    float mv[16];
    if (vb && bool_definitely) {
        // a one at a non-word-aligned byte => must be 1-byte bools
        for (int i = 0; i < 16; i++) mv[i] = bb[i] ? 1.0f : 0.0f;
    } else {
        const unsigned int* u = (const unsigned int*)maskp;
        bool vi = true, vf = true;
        unsigned int uv[16];
        for (int i = 0; i < 16; i++) {
            uv[i] = u[i];
            if (uv[i] > 1u) vi = false;
            if (!(uv[i] == 0u || uv[i] == 0x3f800000u)) vf = false;
        }
        if (vi || vf) {
            for (int i = 0; i < 16; i++) mv[i] = uv[i] ? 1.0f : 0.0f;
        } else if (vb) {
            for (int i = 0; i < 16; i++) mv[i] = bb[i] ? 1.0f : 0.0f;
        } else {
            for (int i = 0; i < 16; i++) mv[i] = uv[i] ? 1.0f : 0.0f;
        }
    }

    for (int b = 0; b < B; b++) {
        float na = 0.0f;
        for (int ci = 0; ci < CI; ci++) {
            float m = mv[b * 8 + (2 * ci + 1)];
            g_instMask[b * CI + ci] = m;
            na += m;
        }
        g_nActive[b] = na;
    }
}

// ---------------------------------------------------------------------------
// Pack: one warp per 128-voxel row. Lane l loads x = l+32w (w=0..3): four
// coalesced 128B warp-loads (MLP=4), four ballots in linear bit order
// (bit l of word w  <->  x = 32w + l), one STG.128 per row.
// Global thread 0 also decodes the mask and zeroes the accumulators.
// ---------------------------------------------------------------------------
__global__ void pack_kernel(const float* __restrict__ targets, const void* maskp) {
    int gt   = blockIdx.x * blockDim.x + threadIdx.x;
    int lane = gt & 31;
    int r    = gt >> 5;                  // row index, 0..ROWS-1
    int y  = r & 127;
    int z  = (r >> 7) & 127;
    int ci = (r >> 14) & 3;
    int b  = r >> 16;
    int ch = 2 * ci + 1;

    size_t base = ((((size_t)(b * 8 + ch)) * DD + z) * HH + y) * WW + lane;

    float v0 = __ldg(&targets[base]);
    float v1 = __ldg(&targets[base + 32]);
    float v2 = __ldg(&targets[base + 64]);
    float v3 = __ldg(&targets[base + 96]);

    unsigned int b0 = __ballot_sync(0xffffffffu, v0 > 0.5f);
    unsigned int b1 = __ballot_sync(0xffffffffu, v1 > 0.5f);
    unsigned int b2 = __ballot_sync(0xffffffffu, v2 > 0.5f);
    unsigned int b3 = __ballot_sync(0xffffffffu, v3 > 0.5f);

    if (lane == 0) {
        uint4 q; q.x = b0; q.y = b1; q.z = b2; q.w = b3;
        *reinterpret_cast<uint4*>(g_tbits + (size_t)r * WPR) = q;
    }

    if (gt == 0) decode_mask_and_zero(maskp);
}

// ---------------------------------------------------------------------------
// Fused double erosion: e2 = erode(erode(t)).
// erode∘erode = erosion by the L1-ball of radius 2 (SE ⊕ SE):
// AND over 13 (dz,dy) row-offsets, each x-eroded to depth 2-|dz|-|dy|.
// ---------------------------------------------------------------------------
__device__ __forceinline__ void load_row128(int bc, int z, int y,
                                            unsigned long long& lo,
                                            unsigned long long& hi) {
    if (((unsigned)z >= (unsigned)DD) | ((unsigned)y >= (unsigned)HH)) {
        lo = 0ull; hi = 0ull; return;   // zero padding, matches jnp.pad
    }
    const uint4 q = *reinterpret_cast<const uint4*>(
        g_tbits + ((size_t)((bc * DD + z) * HH + y)) * WPR);
    lo = (unsigned long long)q.x | ((unsigned long long)q.y << 32);
    hi = (unsigned long long)q.z | ((unsigned long long)q.w << 32);
}

__device__ __forceinline__ void erode_x1(unsigned long long& lo, unsigned long long& hi) {
    // bit k ↔ x=k: (m>>1) pulls x+1, (m<<1) pulls x-1; zero-fill = zero pad
    unsigned long long sl_lo = lo << 1;
    unsigned long long sl_hi = (hi << 1) | (lo >> 63);
    unsigned long long sr_lo = (lo >> 1) | (hi << 63);
    unsigned long long sr_hi = hi >> 1;
    lo &= sl_lo & sr_lo;
    hi &= sl_hi & sr_hi;
}

__global__ void erode2_kernel() {
    int r = blockIdx.x * blockDim.x + threadIdx.x;
    if (r >= ROWS) return;
    int y  = r & 127;
    int z  = (r >> 7) & 127;
    int bc = r >> 14;

    unsigned long long elo, ehi, lo, hi;

    // (0,0): x-erosion depth 2
    load_row128(bc, z, y, elo, ehi);
    erode_x1(elo, ehi);
    erode_x1(elo, ehi);

    // |dz|+|dy| = 1: x-erosion depth 1
    load_row128(bc, z - 1, y, lo, hi); erode_x1(lo, hi); elo &= lo; ehi &= hi;
    load_row128(bc, z + 1, y, lo, hi); erode_x1(lo, hi); elo &= lo; ehi &= hi;
    load_row128(bc, z, y - 1, lo, hi); erode_x1(lo, hi); elo &= lo; ehi &= hi;
    load_row128(bc, z, y + 1, lo, hi); erode_x1(lo, hi); elo &= lo; ehi &= hi;

    // |dz|+|dy| = 2: depth 0
    load_row128(bc, z - 2, y, lo, hi); elo &= lo; ehi &= hi;
    load_row128(bc, z + 2, y, lo, hi); elo &= lo; ehi &= hi;
    load_row128(bc, z, y - 2, lo, hi); elo &= lo; ehi &= hi;
    load_row128(bc, z, y + 2, lo, hi); elo &= lo; ehi &= hi;
    load_row128(bc, z - 1, y - 1, lo, hi); elo &= lo; ehi &= hi;
    load_row128(bc, z - 1, y + 1, lo, hi); elo &= lo; ehi &= hi;
    load_row128(bc, z + 1, y - 1, lo, hi); elo &= lo; ehi &= hi;
    load_row128(bc, z + 1, y + 1, lo, hi); elo &= lo; ehi &= hi;

    uint4 q;
    q.x = (unsigned int)(elo);
    q.y = (unsigned int)(elo >> 32);
    q.z = (unsigned int)(ehi);
    q.w = (unsigned int)(ehi >> 32);
    *reinterpret_cast<uint4*>(g_e2 + ((size_t)r) * WPR) = q;
}

// ---------------------------------------------------------------------------
// Main: fused BCE + boundary weight + masking + reduction + final division
// (last block writes out[0] and resets the completion counter)
// ---------------------------------------------------------------------------
__device__ __forceinline__ float bce_w(float l, unsigned int t, unsigned int bd) {
    float a  = fabsf(l);
    float sp = __logf(1.0f + __expf(-a));            // log1p(e^-|l|), 2x MUFU
    float bce = fmaxf(l, 0.0f) - l * (float)t + sp;
    return bd ? bce * 5.0f : bce;
}

__global__ void __launch_bounds__(256)
main_kernel(const float* __restrict__ logits,
            const float* __restrict__ spatial,
            float* __restrict__ out) {
    int tid = threadIdx.x;
    int bx  = blockIdx.x;                 // 4096 blocks: b(1) z(7) yb(4)
    int b   = bx >> 11;
    int z   = (bx >> 4) & 127;
    int yb  = bx & 15;
    int y   = yb * 8 + (tid >> 5);
    int x4  = (tid & 31) << 2;            // 4 consecutive x per thread
    int sh  = x4 & 31;

    // L2-resident bit words for all 4 channels, issued first so they overlap
    // the DRAM logits loads.
    unsigned int tw[CI], ew[CI];
    int rowBase = ((b * CI) * DD + z) * HH + y;
#pragma unroll
    for (int ci = 0; ci < CI; ci++) {
        unsigned int w = (rowBase + ci * DD * HH) * WPR + (x4 >> 5);
        tw[ci] = __ldg(&g_tbits[w]);
        ew[ci] = __ldg(&g_e2[w]);
    }

    size_t sidx = (((size_t)b * DD + z) * HH + y) * WW + x4;
    float4 s = *reinterpret_cast<const float4*>(spatial + sidx);

    float nA = g_nActive[b];
    float den = nA * (s.x + s.y + s.z + s.w);

    float a0 = 0.f, a1 = 0.f, a2 = 0.f, a3 = 0.f;

#pragma unroll
    for (int ci = 0; ci < CI; ci++) {
        float m = g_instMask[b * CI + ci];
        size_t lidx = ((((size_t)(b * 8 + 2 * ci + 1)) * DD + z) * HH + y) * WW + x4;
        float4 L = *reinterpret_cast<const float4*>(logits + lidx);

        unsigned int tn = (tw[ci] >> sh) & 0xF;
        unsigned int bn = ((tw[ci] & ~ew[ci]) >> sh) & 0xF;

        a0 += m * bce_w(L.x,  tn       & 1u,  bn       & 1u);
        a1 += m * bce_w(L.y, (tn >> 1) & 1u, (bn >> 1) & 1u);
        a2 += m * bce_w(L.z, (tn >> 2) & 1u, (bn >> 2) & 1u);
        a3 += m * bce_w(L.w, (tn >> 3) & 1u, (bn >> 3) & 1u);
    }

    float num = s.x * a0 + s.y * a1 + s.z * a2 + s.w * a3;

    // Warp reduce
#pragma unroll
    for (int o = 16; o > 0; o >>= 1) {
        num += __shfl_down_sync(0xffffffffu, num, o);
        den += __shfl_down_sync(0xffffffffu, den, o);
    }
    __shared__ float s_num[8], s_den[8];
    int wid = tid >> 5, lane = tid & 31;
    if (lane == 0) { s_num[wid] = num; s_den[wid] = den; }
    __syncthreads();

    if (tid == 0) {
        double dn = 0.0, dd = 0.0;
        for (int i = 0; i < 8; i++) { dn += (double)s_num[i]; dd += (double)s_den[i]; }
        atomicAdd(&g_num, dn);
        atomicAdd(&g_den, dd);
        __threadfence();
        unsigned int prev = atomicAdd(&g_done, 1u);
        if (prev == gridDim.x - 1) {
            // Read totals via L2 atomics (plain LDG could hit stale L1: other
            // blocks' contributions were L2 atomicAdds, L1 is not coherent).
            double dnn = atomicAdd(&g_num, 0.0);
            double ddd = atomicAdd(&g_den, 0.0);
            out[0] = (ddd > 0.0) ? (float)(dnn / (ddd < 1.0 ? 1.0 : ddd)) : 0.0f;
            g_done = 0;   // reset for deterministic graph replay
        }
    }
}

// ---------------------------------------------------------------------------
extern "C" void kernel_launch(void* const* d_in, const int* in_sizes, int n_in,
                              void* d_out, int out_size) {
    const float* logits  = (const float*)d_in[0];
    const float* targets = (const float*)d_in[1];
    const void*  maskp   = (const void*)d_in[2];
    const float* spatial = (const float*)d_in[3];
    float* out = (float*)d_out;

    int packThreads = ROWS * 32;                        // one warp per row
    pack_kernel<<<packThreads / 256, 256>>>(targets, maskp);

    erode2_kernel<<<(ROWS + 255) / 256, 256>>>();

    main_kernel<<<B * DD * (HH / 8), 256>>>(logits, spatial, out);
}

// round 10
// speedup vs baseline: 1.1374x; 1.1374x over previous
#include <cuda_runtime.h>
#include <cstdint>

// Problem constants
constexpr int B  = 2;
constexpr int CI = 4;      // instance channels: 1,3,5,7
constexpr int DD = 128, HH = 128, WW = 128;
constexpr int ROWS = B * CI * DD * HH;   // 131072 bit-rows of 128 bits
constexpr int WPR  = WW / 32;            // 4 uint32 words per row

// Device scratch (static; no allocation)
__device__ unsigned int g_tbits[ROWS * WPR];  // packed targets (2 MB)
__device__ unsigned int g_e2[ROWS * WPR];     // double-eroded targets (2 MB)
__device__ double g_num, g_den;
__device__ float g_instMask[B * CI];
__device__ float g_nActive[B];
__device__ unsigned int g_done;               // zero-init; reset by last block

// ---------------------------------------------------------------------------
// Mask decode (dtype-robust: bool bytes / int32 / f32) — runs on one thread
// ---------------------------------------------------------------------------
__device__ void decode_mask_and_zero(const void* maskp) {
    g_num = 0.0; g_den = 0.0;

    const unsigned char* b8 = (const unsigned char*)maskp;
    bool vb = true, bool_definitely = false;
    unsigned char bb[16];
    for (int i = 0; i < 16; i++) {
        bb[i] = b8[i];
        if (bb[i] > 1) vb = false;     // f32 1.0f bytes {0,0,128,63} trip this
    }
    if (vb) {
        for (int i = 0; i < 16; i++)
            if (bb[i] == 1 && (i & 3) != 0) bool_definitely = true;
    }

    float mv[16];
    if (vb && bool_definitely) {
        for (int i = 0; i < 16; i++) mv[i] = bb[i] ? 1.0f : 0.0f;
    } else {
        const unsigned int* u = (const unsigned int*)maskp;
        bool vi = true, vf = true;
        unsigned int uv[16];
        for (int i = 0; i < 16; i++) {
            uv[i] = u[i];
            if (uv[i] > 1u) vi = false;
            if (!(uv[i] == 0u || uv[i] == 0x3f800000u)) vf = false;
        }
        if (vi || vf) {
            for (int i = 0; i < 16; i++) mv[i] = uv[i] ? 1.0f : 0.0f;
        } else if (vb) {
            for (int i = 0; i < 16; i++) mv[i] = bb[i] ? 1.0f : 0.0f;
        } else {
            for (int i = 0; i < 16; i++) mv[i] = uv[i] ? 1.0f : 0.0f;
        }
    }

    for (int b = 0; b < B; b++) {
        float na = 0.0f;
        for (int ci = 0; ci < CI; ci++) {
            float m = mv[b * 8 + (2 * ci + 1)];
            g_instMask[b * CI + ci] = m;
            na += m;
        }
        g_nActive[b] = na;
    }
}

// Spread 8 bits to every 4th bit of a 32-bit word (morton-4 expansion)
__device__ __forceinline__ unsigned int spread4(unsigned int x) {
    x &= 0xFFu;
    x = (x | (x << 12)) & 0x000F000Fu;
    x = (x | (x << 6))  & 0x03030303u;
    x = (x | (x << 3))  & 0x11111111u;
    return x;
}

// ---------------------------------------------------------------------------
// Pack: one warp per FOUR 128-voxel rows (consecutive y, same b/ci/z since
// row-group is 4-aligned and HH=128). Lane l loads float4 at x=4l for each of
// the 4 rows -> 4 independent LDG.128 per thread in flight (64B/thread).
// Bit assembly per row: nibble -> 4 ballots -> lanes 0-3 morton-reassemble
// word w from byte w of each ballot (bit x=4l+k -> word (x>>5), pos x&31).
// Global thread 0 also decodes the mask and zeroes the accumulators.
// ---------------------------------------------------------------------------
__global__ void __launch_bounds__(256)
pack_kernel(const float* __restrict__ targets, const void* maskp) {
    int gt   = blockIdx.x * blockDim.x + threadIdx.x;
    int lane = gt & 31;
    int r0   = (gt >> 5) << 2;           // first of 4 rows for this warp
    int y0 = r0 & 127;
    int z  = (r0 >> 7) & 127;
    int ci = (r0 >> 14) & 3;
    int b  = r0 >> 16;
    int ch = 2 * ci + 1;

    size_t base = ((((size_t)(b * 8 + ch)) * DD + z) * HH + y0) * WW + 4 * lane;

    // 4 independent vector loads, all issued before any dependency
    float4 v0 = __ldg(reinterpret_cast<const float4*>(targets + base));
    float4 v1 = __ldg(reinterpret_cast<const float4*>(targets + base + WW));
    float4 v2 = __ldg(reinterpret_cast<const float4*>(targets + base + 2 * WW));
    float4 v3 = __ldg(reinterpret_cast<const float4*>(targets + base + 3 * WW));

#pragma unroll
    for (int j = 0; j < 4; j++) {
        float4 v = (j == 0) ? v0 : (j == 1) ? v1 : (j == 2) ? v2 : v3;
        unsigned int n = (v.x > 0.5f ? 1u : 0u)
                       | (v.y > 0.5f ? 2u : 0u)
                       | (v.z > 0.5f ? 4u : 0u)
                       | (v.w > 0.5f ? 8u : 0u);
        unsigned int B0 = __ballot_sync(0xffffffffu, n & 1u);
        unsigned int B1 = __ballot_sync(0xffffffffu, n & 2u);
        unsigned int B2 = __ballot_sync(0xffffffffu, n & 4u);
        unsigned int B3 = __ballot_sync(0xffffffffu, n & 8u);
        if (lane < 4) {
            unsigned int word = spread4(B0 >> (8 * lane))
                              | (spread4(B1 >> (8 * lane)) << 1)
                              | (spread4(B2 >> (8 * lane)) << 2)
                              | (spread4(B3 >> (8 * lane)) << 3);
            g_tbits[(size_t)(r0 + j) * WPR + lane] = word;   // 16B coalesced
        }
    }

    if (gt == 0) decode_mask_and_zero(maskp);
}

// ---------------------------------------------------------------------------
// Fused double erosion: e2 = erode(erode(t)).
// erode∘erode = erosion by the L1-ball of radius 2 (SE ⊕ SE):
// AND over 13 (dz,dy) row-offsets, each x-eroded to depth 2-|dz|-|dy|.
// ---------------------------------------------------------------------------
__device__ __forceinline__ void load_row128(int bc, int z, int y,
                                            unsigned long long& lo,
                                            unsigned long long& hi) {
    if (((unsigned)z >= (unsigned)DD) | ((unsigned)y >= (unsigned)HH)) {
        lo = 0ull; hi = 0ull; return;   // zero padding, matches jnp.pad
    }
    const uint4 q = *reinterpret_cast<const uint4*>(
        g_tbits + ((size_t)((bc * DD + z) * HH + y)) * WPR);
    lo = (unsigned long long)q.x | ((unsigned long long)q.y << 32);
    hi = (unsigned long long)q.z | ((unsigned long long)q.w << 32);
}

__device__ __forceinline__ void erode_x1(unsigned long long& lo, unsigned long long& hi) {
    // bit k ↔ x=k: (m>>1) pulls x+1, (m<<1) pulls x-1; zero-fill = zero pad
    unsigned long long sl_lo = lo << 1;
    unsigned long long sl_hi = (hi << 1) | (lo >> 63);
    unsigned long long sr_lo = (lo >> 1) | (hi << 63);
    unsigned long long sr_hi = hi >> 1;
    lo &= sl_lo & sr_lo;
    hi &= sl_hi & sr_hi;
}

__global__ void erode2_kernel() {
    int r = blockIdx.x * blockDim.x + threadIdx.x;
    if (r >= ROWS) return;
    int y  = r & 127;
    int z  = (r >> 7) & 127;
    int bc = r >> 14;

    unsigned long long elo, ehi, lo, hi;

    // (0,0): x-erosion depth 2
    load_row128(bc, z, y, elo, ehi);
    erode_x1(elo, ehi);
    erode_x1(elo, ehi);

    // |dz|+|dy| = 1: x-erosion depth 1
    load_row128(bc, z - 1, y, lo, hi); erode_x1(lo, hi); elo &= lo; ehi &= hi;
    load_row128(bc, z + 1, y, lo, hi); erode_x1(lo, hi); elo &= lo; ehi &= hi;
    load_row128(bc, z, y - 1, lo, hi); erode_x1(lo, hi); elo &= lo; ehi &= hi;
    load_row128(bc, z, y + 1, lo, hi); erode_x1(lo, hi); elo &= lo; ehi &= hi;

    // |dz|+|dy| = 2: depth 0
    load_row128(bc, z - 2, y, lo, hi); elo &= lo; ehi &= hi;
    load_row128(bc, z + 2, y, lo, hi); elo &= lo; ehi &= hi;
    load_row128(bc, z, y - 2, lo, hi); elo &= lo; ehi &= hi;
    load_row128(bc, z, y + 2, lo, hi); elo &= lo; ehi &= hi;
    load_row128(bc, z - 1, y - 1, lo, hi); elo &= lo; ehi &= hi;
    load_row128(bc, z - 1, y + 1, lo, hi); elo &= lo; ehi &= hi;
    load_row128(bc, z + 1, y - 1, lo, hi); elo &= lo; ehi &= hi;
    load_row128(bc, z + 1, y + 1, lo, hi); elo &= lo; ehi &= hi;

    uint4 q;
    q.x = (unsigned int)(elo);
    q.y = (unsigned int)(elo >> 32);
    q.z = (unsigned int)(ehi);
    q.w = (unsigned int)(ehi >> 32);
    *reinterpret_cast<uint4*>(g_e2 + ((size_t)r) * WPR) = q;
}

// ---------------------------------------------------------------------------
// Main: fused BCE + boundary weight + masking + reduction + final division
// (last block writes out[0] and resets the completion counter)
// ---------------------------------------------------------------------------
__device__ __forceinline__ float bce_w(float l, unsigned int t, unsigned int bd) {
    float a  = fabsf(l);
    float sp = __logf(1.0f + __expf(-a));            // log1p(e^-|l|), 2x MUFU
    float bce = fmaxf(l, 0.0f) - l * (float)t + sp;
    return bd ? bce * 5.0f : bce;
}

__global__ void __launch_bounds__(256)
main_kernel(const float* __restrict__ logits,
            const float* __restrict__ spatial,
            float* __restrict__ out) {
    int tid = threadIdx.x;
    int bx  = blockIdx.x;                 // 4096 blocks: b(1) z(7) yb(4)
    int b   = bx >> 11;
    int z   = (bx >> 4) & 127;
    int yb  = bx & 15;
    int y   = yb * 8 + (tid >> 5);
    int x4  = (tid & 31) << 2;            // 4 consecutive x per thread
    int sh  = x4 & 31;

    // Issue ALL loads before any compute: 8 L2-resident bit words, 4 DRAM
    // logits float4s (16 MiB apart), 1 spatial float4 -> MLP_p1 ~ 13.
    unsigned int tw[CI], ew[CI];
    int rowBase = ((b * CI) * DD + z) * HH + y;
#pragma unroll
    for (int ci = 0; ci < CI; ci++) {
        unsigned int w = (rowBase + ci * DD * HH) * WPR + (x4 >> 5);
        tw[ci] = __ldg(&g_tbits[w]);
        ew[ci] = __ldg(&g_e2[w]);
    }

    float4 L[CI];
#pragma unroll
    for (int ci = 0; ci < CI; ci++) {
        size_t lidx = ((((size_t)(b * 8 + 2 * ci + 1)) * DD + z) * HH + y) * WW + x4;
        L[ci] = *reinterpret_cast<const float4*>(logits + lidx);
    }

    size_t sidx = (((size_t)b * DD + z) * HH + y) * WW + x4;
    float4 s = *reinterpret_cast<const float4*>(spatial + sidx);

    float nA = g_nActive[b];
    float den = nA * (s.x + s.y + s.z + s.w);

    float a0 = 0.f, a1 = 0.f, a2 = 0.f, a3 = 0.f;

#pragma unroll
    for (int ci = 0; ci < CI; ci++) {
        float m = g_instMask[b * CI + ci];
        unsigned int tn = (tw[ci] >> sh) & 0xF;
        unsigned int bn = ((tw[ci] & ~ew[ci]) >> sh) & 0xF;

        a0 += m * bce_w(L[ci].x,  tn       & 1u,  bn       & 1u);
        a1 += m * bce_w(L[ci].y, (tn >> 1) & 1u, (bn >> 1) & 1u);
        a2 += m * bce_w(L[ci].z, (tn >> 2) & 1u, (bn >> 2) & 1u);
        a3 += m * bce_w(L[ci].w, (tn >> 3) & 1u, (bn >> 3) & 1u);
    }

    float num = s.x * a0 + s.y * a1 + s.z * a2 + s.w * a3;

    // Warp reduce
#pragma unroll
    for (int o = 16; o > 0; o >>= 1) {
        num += __shfl_down_sync(0xffffffffu, num, o);
        den += __shfl_down_sync(0xffffffffu, den, o);
    }
    __shared__ float s_num[8], s_den[8];
    int wid = tid >> 5, lane = tid & 31;
    if (lane == 0) { s_num[wid] = num; s_den[wid] = den; }
    __syncthreads();

    if (tid == 0) {
        double dn = 0.0, dd = 0.0;
        for (int i = 0; i < 8; i++) { dn += (double)s_num[i]; dd += (double)s_den[i]; }
        atomicAdd(&g_num, dn);
        atomicAdd(&g_den, dd);
        __threadfence();
        unsigned int prev = atomicAdd(&g_done, 1u);
        if (prev == gridDim.x - 1) {
            // Read totals via L2 atomics (plain LDG could hit stale L1: other
            // blocks' contributions were L2 atomicAdds, L1 is not coherent).
            double dnn = atomicAdd(&g_num, 0.0);
            double ddd = atomicAdd(&g_den, 0.0);
            out[0] = (ddd > 0.0) ? (float)(dnn / (ddd < 1.0 ? 1.0 : ddd)) : 0.0f;
            g_done = 0;   // reset for deterministic graph replay
        }
    }
}

// ---------------------------------------------------------------------------
extern "C" void kernel_launch(void* const* d_in, const int* in_sizes, int n_in,
                              void* d_out, int out_size) {
    const float* logits  = (const float*)d_in[0];
    const float* targets = (const float*)d_in[1];
    const void*  maskp   = (const void*)d_in[2];
    const float* spatial = (const float*)d_in[3];
    float* out = (float*)d_out;

    // pack: one warp per 4 rows -> ROWS/32 blocks of 256 threads
    pack_kernel<<<ROWS / 32, 256>>>(targets, maskp);

    erode2_kernel<<<(ROWS + 255) / 256, 256>>>();

    main_kernel<<<B * DD * (HH / 8), 256>>>(logits, spatial, out);
}

// round 14
// speedup vs baseline: 1.1383x; 1.0007x over previous
#include <cuda_runtime.h>
#include <cstdint>

// Problem constants
constexpr int B  = 2;
constexpr int CI = 4;      // instance channels: 1,3,5,7
constexpr int DD = 128, HH = 128, WW = 128;
constexpr int ROWS = B * CI * DD * HH;   // 131072 bit-rows of 128 bits
constexpr int WPR  = WW / 32;            // 4 uint32 words per row

// Device scratch (static; no allocation)
__device__ unsigned int g_tbits[ROWS * WPR];  // packed targets (2 MB)
__device__ unsigned int g_e2[ROWS * WPR];     // double-eroded targets (2 MB)
__device__ double g_num, g_den;
__device__ float g_instMask[B * CI];
__device__ float g_nActive[B];
__device__ unsigned int g_done;               // zero-init; reset by last block

// ---------------------------------------------------------------------------
// Mask decode (dtype-robust: bool bytes / int32 / f32) — runs on one thread
// ---------------------------------------------------------------------------
__device__ void decode_mask_and_zero(const void* maskp) {
    g_num = 0.0; g_den = 0.0;

    const unsigned char* b8 = (const unsigned char*)maskp;
    bool vb = true, bool_definitely = false;
    unsigned char bb[16];
    for (int i = 0; i < 16; i++) {
        bb[i] = b8[i];
        if (bb[i] > 1) vb = false;     // f32 1.0f bytes {0,0,128,63} trip this
    }
    if (vb) {
        for (int i = 0; i < 16; i++)
            if (bb[i] == 1 && (i & 3) != 0) bool_definitely = true;
    }

    float mv[16];
    if (vb && bool_definitely) {
        for (int i = 0; i < 16; i++) mv[i] = bb[i] ? 1.0f : 0.0f;
    } else {
        const unsigned int* u = (const unsigned int*)maskp;
        bool vi = true, vf = true;
        unsigned int uv[16];
        for (int i = 0; i < 16; i++) {
            uv[i] = u[i];
            if (uv[i] > 1u) vi = false;
            if (!(uv[i] == 0u || uv[i] == 0x3f800000u)) vf = false;
        }
        if (vi || vf) {
            for (int i = 0; i < 16; i++) mv[i] = uv[i] ? 1.0f : 0.0f;
        } else if (vb) {
            for (int i = 0; i < 16; i++) mv[i] = bb[i] ? 1.0f : 0.0f;
        } else {
            for (int i = 0; i < 16; i++) mv[i] = uv[i] ? 1.0f : 0.0f;
        }
    }

    for (int b = 0; b < B; b++) {
        float na = 0.0f;
        for (int ci = 0; ci < CI; ci++) {
            float m = mv[b * 8 + (2 * ci + 1)];
            g_instMask[b * CI + ci] = m;
            na += m;
        }
        g_nActive[b] = na;
    }
}

// Spread 8 bits to every 4th bit of a 32-bit word (morton-4 expansion)
__device__ __forceinline__ unsigned int spread4(unsigned int x) {
    x &= 0xFFu;
    x = (x | (x << 12)) & 0x000F000Fu;
    x = (x | (x << 6))  & 0x03030303u;
    x = (x | (x << 3))  & 0x11111111u;
    return x;
}

// ---------------------------------------------------------------------------
// Pack: one warp per EIGHT 128-voxel rows (consecutive y, same b/ci/z since
// the 8-row group is 8-aligned and HH=128). Lane l loads float4 at x=4l for
// each of the 8 rows -> 8 independent LDG.128 per thread (128B in flight)
// before any warp-collective. Per row: nibble -> 4 ballots -> lanes 0-3
// morton-reassemble word w from byte w of each ballot (validated R10).
// Global thread 0 also decodes the mask and zeroes the accumulators.
// ---------------------------------------------------------------------------
__global__ void __launch_bounds__(256)
pack_kernel(const float* __restrict__ targets, const void* maskp) {
    int gt   = blockIdx.x * blockDim.x + threadIdx.x;
    int lane = gt & 31;
    int r0   = (gt >> 5) << 3;           // first of 8 rows for this warp
    int y0 = r0 & 127;
    int z  = (r0 >> 7) & 127;
    int ci = (r0 >> 14) & 3;
    int b  = r0 >> 16;
    int ch = 2 * ci + 1;

    size_t base = ((((size_t)(b * 8 + ch)) * DD + z) * HH + y0) * WW + 4 * lane;

    // 8 independent coalesced vector loads, all issued before any dependency
    float4 v[8];
#pragma unroll
    for (int j = 0; j < 8; j++)
        v[j] = __ldg(reinterpret_cast<const float4*>(targets + base + (size_t)j * WW));

#pragma unroll
    for (int j = 0; j < 8; j++) {
        unsigned int n = (v[j].x > 0.5f ? 1u : 0u)
                       | (v[j].y > 0.5f ? 2u : 0u)
                       | (v[j].z > 0.5f ? 4u : 0u)
                       | (v[j].w > 0.5f ? 8u : 0u);
        unsigned int B0 = __ballot_sync(0xffffffffu, n & 1u);
        unsigned int B1 = __ballot_sync(0xffffffffu, n & 2u);
        unsigned int B2 = __ballot_sync(0xffffffffu, n & 4u);
        unsigned int B3 = __ballot_sync(0xffffffffu, n & 8u);
        if (lane < 4) {
            unsigned int word = spread4(B0 >> (8 * lane))
                              | (spread4(B1 >> (8 * lane)) << 1)
                              | (spread4(B2 >> (8 * lane)) << 2)
                              | (spread4(B3 >> (8 * lane)) << 3);
            g_tbits[(size_t)(r0 + j) * WPR + lane] = word;   // 16B coalesced
        }
    }

    if (gt == 0) decode_mask_and_zero(maskp);
}

// ---------------------------------------------------------------------------
// Fused double erosion: e2 = erode(erode(t)).
// erode∘erode = erosion by the L1-ball of radius 2 (SE ⊕ SE):
// AND over 13 (dz,dy) row-offsets, each x-eroded to depth 2-|dz|-|dy|.
// ---------------------------------------------------------------------------
__device__ __forceinline__ void load_row128(int bc, int z, int y,
                                            unsigned long long& lo,
                                            unsigned long long& hi) {
    if (((unsigned)z >= (unsigned)DD) | ((unsigned)y >= (unsigned)HH)) {
        lo = 0ull; hi = 0ull; return;   // zero padding, matches jnp.pad
    }
    const uint4 q = *reinterpret_cast<const uint4*>(
        g_tbits + ((size_t)((bc * DD + z) * HH + y)) * WPR);
    lo = (unsigned long long)q.x | ((unsigned long long)q.y << 32);
    hi = (unsigned long long)q.z | ((unsigned long long)q.w << 32);
}

__device__ __forceinline__ void erode_x1(unsigned long long& lo, unsigned long long& hi) {
    // bit k ↔ x=k: (m>>1) pulls x+1, (m<<1) pulls x-1; zero-fill = zero pad
    unsigned long long sl_lo = lo << 1;
    unsigned long long sl_hi = (hi << 1) | (lo >> 63);
    unsigned long long sr_lo = (lo >> 1) | (hi << 63);
    unsigned long long sr_hi = hi >> 1;
    lo &= sl_lo & sr_lo;
    hi &= sl_hi & sr_hi;
}

__global__ void erode2_kernel() {
    int r = blockIdx.x * blockDim.x + threadIdx.x;
    if (r >= ROWS) return;
    int y  = r & 127;
    int z  = (r >> 7) & 127;
    int bc = r >> 14;

    unsigned long long elo, ehi, lo, hi;

    // (0,0): x-erosion depth 2
    load_row128(bc, z, y, elo, ehi);
    erode_x1(elo, ehi);
    erode_x1(elo, ehi);

    // |dz|+|dy| = 1: x-erosion depth 1
    load_row128(bc, z - 1, y, lo, hi); erode_x1(lo, hi); elo &= lo; ehi &= hi;
    load_row128(bc, z + 1, y, lo, hi); erode_x1(lo, hi); elo &= lo; ehi &= hi;
    load_row128(bc, z, y - 1, lo, hi); erode_x1(lo, hi); elo &= lo; ehi &= hi;
    load_row128(bc, z, y + 1, lo, hi); erode_x1(lo, hi); elo &= lo; ehi &= hi;

    // |dz|+|dy| = 2: depth 0
    load_row128(bc, z - 2, y, lo, hi); elo &= lo; ehi &= hi;
    load_row128(bc, z + 2, y, lo, hi); elo &= lo; ehi &= hi;
    load_row128(bc, z, y - 2, lo, hi); elo &= lo; ehi &= hi;
    load_row128(bc, z, y + 2, lo, hi); elo &= lo; ehi &= hi;
    load_row128(bc, z - 1, y - 1, lo, hi); elo &= lo; ehi &= hi;
    load_row128(bc, z - 1, y + 1, lo, hi); elo &= lo; ehi &= hi;
    load_row128(bc, z + 1, y - 1, lo, hi); elo &= lo; ehi &= hi;
    load_row128(bc, z + 1, y + 1, lo, hi); elo &= lo; ehi &= hi;

    uint4 q;
    q.x = (unsigned int)(elo);
    q.y = (unsigned int)(elo >> 32);
    q.z = (unsigned int)(ehi);
    q.w = (unsigned int)(ehi >> 32);
    *reinterpret_cast<uint4*>(g_e2 + ((size_t)r) * WPR) = q;
}

// ---------------------------------------------------------------------------
// Main: fused BCE + boundary weight + masking + reduction + final division.
// 8 x-positions per thread: per channel 2 independent DRAM float4s -> 8 DRAM
// loads + 2 spatial float4s + 8 L2 bit words all in flight before compute.
// ---------------------------------------------------------------------------
__device__ __forceinline__ float bce_w(float l, unsigned int t, unsigned int bd) {
    float a  = fabsf(l);
    float sp = __logf(1.0f + __expf(-a));            // log1p(e^-|l|), 2x MUFU
    float bce = fmaxf(l, 0.0f) - l * (float)t + sp;
    return bd ? bce * 5.0f : bce;
}

__global__ void __launch_bounds__(256)
main_kernel(const float* __restrict__ logits,
            const float* __restrict__ spatial,
            float* __restrict__ out) {
    int tid = threadIdx.x;
    int bx  = blockIdx.x;                 // 2048 blocks: b(1) z(7) yg(3)
    int b   = bx >> 10;
    int z   = (bx >> 3) & 127;
    int yg  = bx & 7;
    int y   = yg * 16 + (tid >> 4);       // 16 y-rows per block
    int x8  = (tid & 15) << 3;            // 8 consecutive x per thread
    int sh  = x8 & 31;                    // 0,8,16,24
    int wi  = x8 >> 5;

    // L2-resident bit words for all 4 channels
    unsigned int tw[CI], ew[CI];
    int rowBase = ((b * CI) * DD + z) * HH + y;
#pragma unroll
    for (int ci = 0; ci < CI; ci++) {
        unsigned int w = (rowBase + ci * DD * HH) * WPR + wi;
        tw[ci] = __ldg(&g_tbits[w]);
        ew[ci] = __ldg(&g_e2[w]);
    }

    // 8 independent DRAM float4s (4 channels x 2), then 2 spatial float4s
    float4 L[CI][2];
#pragma unroll
    for (int ci = 0; ci < CI; ci++) {
        size_t lidx = ((((size_t)(b * 8 + 2 * ci + 1)) * DD + z) * HH + y) * WW + x8;
        L[ci][0] = *reinterpret_cast<const float4*>(logits + lidx);
        L[ci][1] = *reinterpret_cast<const float4*>(logits + lidx + 4);
    }

    size_t sidx = (((size_t)b * DD + z) * HH + y) * WW + x8;
    float4 s0 = *reinterpret_cast<const float4*>(spatial + sidx);
    float4 s1 = *reinterpret_cast<const float4*>(spatial + sidx + 4);

    float nA = g_nActive[b];
    float den = nA * (s0.x + s0.y + s0.z + s0.w + s1.x + s1.y + s1.z + s1.w);

    float acc[8] = {0.f, 0.f, 0.f, 0.f, 0.f, 0.f, 0.f, 0.f};

#pragma unroll
    for (int ci = 0; ci < CI; ci++) {
        float m = g_instMask[b * CI + ci];
        unsigned int tn = (tw[ci] >> sh) & 0xFFu;
        unsigned int bn = ((tw[ci] & ~ew[ci]) >> sh) & 0xFFu;

        acc[0] += m * bce_w(L[ci][0].x,  tn       & 1u,  bn       & 1u);
        acc[1] += m * bce_w(L[ci][0].y, (tn >> 1) & 1u, (bn >> 1) & 1u);
        acc[2] += m * bce_w(L[ci][0].z, (tn >> 2) & 1u, (bn >> 2) & 1u);
        acc[3] += m * bce_w(L[ci][0].w, (tn >> 3) & 1u, (bn >> 3) & 1u);
        acc[4] += m * bce_w(L[ci][1].x, (tn >> 4) & 1u, (bn >> 4) & 1u);
        acc[5] += m * bce_w(L[ci][1].y, (tn >> 5) & 1u, (bn >> 5) & 1u);
        acc[6] += m * bce_w(L[ci][1].z, (tn >> 6) & 1u, (bn >> 6) & 1u);
        acc[7] += m * bce_w(L[ci][1].w, (tn >> 7) & 1u, (bn >> 7) & 1u);
    }

    float num = s0.x * acc[0] + s0.y * acc[1] + s0.z * acc[2] + s0.w * acc[3]
              + s1.x * acc[4] + s1.y * acc[5] + s1.z * acc[6] + s1.w * acc[7];

    // Warp reduce
#pragma unroll
    for (int o = 16; o > 0; o >>= 1) {
        num += __shfl_down_sync(0xffffffffu, num, o);
        den += __shfl_down_sync(0xffffffffu, den, o);
    }
    __shared__ float s_num[8], s_den[8];
    int wid = tid >> 5, lane = tid & 31;
    if (lane == 0) { s_num[wid] = num; s_den[wid] = den; }
    __syncthreads();

    if (tid == 0) {
        double dn = 0.0, dd = 0.0;
        for (int i = 0; i < 8; i++) { dn += (double)s_num[i]; dd += (double)s_den[i]; }
        atomicAdd(&g_num, dn);
        atomicAdd(&g_den, dd);
        __threadfence();
        unsigned int prev = atomicAdd(&g_done, 1u);
        if (prev == gridDim.x - 1) {
            // Read totals via L2 atomics (plain LDG could hit stale L1: other
            // blocks' contributions were L2 atomicAdds, L1 is not coherent).
            double dnn = atomicAdd(&g_num, 0.0);
            double ddd = atomicAdd(&g_den, 0.0);
            out[0] = (ddd > 0.0) ? (float)(dnn / (ddd < 1.0 ? 1.0 : ddd)) : 0.0f;
            g_done = 0;   // reset for deterministic graph replay
        }
    }
}

// ---------------------------------------------------------------------------
extern "C" void kernel_launch(void* const* d_in, const int* in_sizes, int n_in,
                              void* d_out, int out_size) {
    const float* logits  = (const float*)d_in[0];
    const float* targets = (const float*)d_in[1];
    const void*  maskp   = (const void*)d_in[2];
    const float* spatial = (const float*)d_in[3];
    float* out = (float*)d_out;

    // pack: one warp per 8 rows -> ROWS/64 blocks of 256 threads
    pack_kernel<<<ROWS / 64, 256>>>(targets, maskp);

    erode2_kernel<<<(ROWS + 255) / 256, 256>>>();

    // main: 8 x per thread -> 2048 blocks
    main_kernel<<<B * DD * (HH / 16), 256>>>(logits, spatial, out);
}